// round 14
// baseline (speedup 1.0000x reference)
#include <cuda_runtime.h>
#include <math.h>

#define NMAX 4096
#define NPIX (96*96)
#define NBLK 144
#define NWORDS (NMAX/32)
#define NSEG 16
#define PB 32
#define LOG2E 1.4426950408889634f
#define LOG2_INV255 -7.9943534f

// ---- packed scratch (device globals) ----
__device__ float4 g_p0[NMAX];   // u0, u1, bx2, by2
__device__ float4 g_p1[NMAX];   // hA2, hB2, hC2, la2 (log2-scaled)
__device__ float4 g_p2[NMAX];   // cr, cg, cb, 0
__device__ unsigned long long g_key[NMAX];
__device__ float4 o_p0[NMAX];
__device__ float4 o_p1[NMAX];
__device__ float4 o_p2[NMAX];

// grid barrier state (144 blocks, 1/SM on 148 SMs -> all co-resident)
__device__ int g_cnt;
__device__ volatile unsigned g_gen;

__device__ __forceinline__ void gbar(unsigned& gen)
{
    __syncthreads();
    if (threadIdx.x == 0) {
        __threadfence();
        if (atomicAdd(&g_cnt, 1) == NBLK - 1) {
            g_cnt = 0;
            __threadfence();
            g_gen = gen + 1;
        } else {
            while (g_gen == gen) __nanosleep(32);
            __threadfence();
        }
    }
    __syncthreads();
    gen++;
}

__device__ __forceinline__ float exp2_approx(float x)
{
    float r;
    asm("ex2.approx.ftz.f32 %0, %1;" : "=f"(r) : "f"(x));
    return r;
}

// smem byte offsets (aliased across phases)
#define OFF_WSUM   512
#define OFF_SLIST  544
#define OFF_STA    8736
#define OFF_STB    16928
#define OFF_STC    25120
#define OFF_PART   27168
#define SBUF_BYTES 43648

__global__ void __launch_bounds__(512, 1)
fused_kernel(const float* __restrict__ pws,
             const float* __restrict__ lows,
             const float* __restrict__ highs,
             const float* __restrict__ araw,
             const float* __restrict__ sraw,
             const float* __restrict__ qraw,
             const float* __restrict__ Rcw,
             const float* __restrict__ tcw,
             const float* __restrict__ cam,
             float* __restrict__ out,
             int n)
{
    __shared__ __align__(16) unsigned char sbuf[SBUF_BYTES];
    unsigned gen = g_gen;   // read pre-arrival by every block (release can't precede all arrivals)

    int b = blockIdx.x, tid = threadIdx.x;
    int lane = tid & 31, warp = tid >> 5;
    int base = b * PB;

    // ================= Phase 1: preprocess (blocks 0..127, 32 gaussians each) =================
    if (b < 128 && base < n) {
        float* s_high = (float*)sbuf;
        float* s_pw   = s_high + PB*45;
        float* s_low  = s_pw + PB*3;
        float* s_sr   = s_low + PB*3;
        float* s_q    = s_sr + PB*3;
        float* s_a    = s_q + PB*4;

        if (base + PB <= n) {
            const float4* H4 = (const float4*)(highs + base*45);
            for (int k = tid; k < PB*45/4; k += 512) ((float4*)s_high)[k] = H4[k];
            if (tid < PB*3/4) {
                ((float4*)s_pw)[tid]  = ((const float4*)(pws  + base*3))[tid];
                ((float4*)s_low)[tid] = ((const float4*)(lows + base*3))[tid];
                ((float4*)s_sr)[tid]  = ((const float4*)(sraw + base*3))[tid];
            }
            if (tid < PB)   ((float4*)s_q)[tid] = ((const float4*)(qraw + base*4))[tid];
            if (tid < PB/4) ((float4*)s_a)[tid] = ((const float4*)(araw + base))[tid];
        } else {
            for (int k = tid; k < PB*45 && base*45 + k < n*45; k += 512) s_high[k] = highs[base*45+k];
            for (int k = tid; k < PB*3 && base*3 + k < n*3; k += 512) {
                s_pw[k] = pws[base*3+k]; s_low[k] = lows[base*3+k]; s_sr[k] = sraw[base*3+k];
            }
            for (int k = tid; k < PB*4 && base*4 + k < n*4; k += 512) s_q[k] = qraw[base*4+k];
            if (tid < PB && base + tid < n) s_a[tid] = araw[base + tid];
        }
        __syncthreads();

        int i = base + tid;
        if (tid < PB && i < n) {
            float fx = cam[0], fy = cam[1], cx = cam[2], cy = cam[3];
            float R00=Rcw[0],R01=Rcw[1],R02=Rcw[2];
            float R10=Rcw[3],R11=Rcw[4],R12=Rcw[5];
            float R20=Rcw[6],R21=Rcw[7],R22=Rcw[8];
            float t0=tcw[0],t1=tcw[1],t2=tcw[2];

            float pwx=s_pw[3*tid], pwy=s_pw[3*tid+1], pwz=s_pw[3*tid+2];
            float pcx = R00*pwx + R01*pwy + R02*pwz + t0;
            float pcy = R10*pwx + R11*pwy + R12*pwz + t1;
            float pcz = R20*pwx + R21*pwy + R22*pwz + t2;
            float depth = pcz;
            float zs = (depth > 1e-6f) ? depth : 1e-6f;
            float inv_z = 1.0f / zs;
            float u0 = fx * pcx * inv_z + cx;
            float u1 = fy * pcy * inv_z + cy;

            float s0 = __expf(s_sr[3*tid]), s1 = __expf(s_sr[3*tid+1]), s2 = __expf(s_sr[3*tid+2]);
            float qw=s_q[4*tid], qx=s_q[4*tid+1], qy=s_q[4*tid+2], qz=s_q[4*tid+3];
            float qn = rsqrtf(qw*qw + qx*qx + qy*qy + qz*qz);
            qw*=qn; qx*=qn; qy*=qn; qz*=qn;
            float r00 = 1.f-2.f*(qy*qy+qz*qz), r01 = 2.f*(qx*qy-qw*qz), r02 = 2.f*(qx*qz+qw*qy);
            float r10 = 2.f*(qx*qy+qw*qz), r11 = 1.f-2.f*(qx*qx+qz*qz), r12 = 2.f*(qy*qz-qw*qx);
            float r20 = 2.f*(qx*qz-qw*qy), r21 = 2.f*(qy*qz+qw*qx), r22 = 1.f-2.f*(qx*qx+qy*qy);

            float v0=s0*s0, v1=s1*s1, v2=s2*s2;
            float c00 = v0*r00*r00 + v1*r01*r01 + v2*r02*r02;
            float c01 = v0*r00*r10 + v1*r01*r11 + v2*r02*r12;
            float c02 = v0*r00*r20 + v1*r01*r21 + v2*r02*r22;
            float c11 = v0*r10*r10 + v1*r11*r11 + v2*r12*r12;
            float c12 = v0*r10*r20 + v1*r11*r21 + v2*r12*r22;
            float c22 = v0*r20*r20 + v1*r21*r21 + v2*r22*r22;

            float limx = 1.3f * (96.0f / (2.0f*fx));
            float limy = 1.3f * (96.0f / (2.0f*fy));
            float txc = fminf(fmaxf(pcx*inv_z, -limx), limx) * zs;
            float tyc = fminf(fmaxf(pcy*inv_z, -limy), limy) * zs;
            float J00 = fx*inv_z, J02 = -fx*txc*inv_z*inv_z;
            float J11 = fy*inv_z, J12 = -fy*tyc*inv_z*inv_z;

            float T00 = J00*R00 + J02*R20, T01 = J00*R01 + J02*R21, T02 = J00*R02 + J02*R22;
            float T10 = J11*R10 + J12*R20, T11 = J11*R11 + J12*R21, T12 = J11*R12 + J12*R22;

            float m00 = T00*c00 + T01*c01 + T02*c02;
            float m01 = T00*c01 + T01*c11 + T02*c12;
            float m02 = T00*c02 + T01*c12 + T02*c22;
            float m10 = T10*c00 + T11*c01 + T12*c02;
            float m11 = T10*c01 + T11*c11 + T12*c12;
            float m12 = T10*c02 + T11*c12 + T12*c22;

            float A  = m00*T00 + m01*T01 + m02*T02 + 0.3f;
            float Bb = m00*T10 + m01*T11 + m02*T12;
            float Cc = m10*T10 + m11*T11 + m12*T12 + 0.3f;

            float det  = A*Cc - Bb*Bb;
            float idet = 1.0f / det;
            float hA2 = -0.5f * Cc * idet * LOG2E;
            float hC2 = -0.5f * A  * idet * LOG2E;
            float hB2 =  Bb * idet * LOG2E;

            float mid = 0.5f * (A + Cc);
            float lam = mid + sqrtf(fmaxf(mid*mid - det, 0.1f));
            float radius = ceilf(3.0f * sqrtf(lam));
            float* out_areas = out + 3 * NPIX;
            out_areas[2*i]   = radius;
            out_areas[2*i+1] = radius;

            float alpha = 1.0f / (1.0f + __expf(-s_a[tid]));
            if (!(depth > 0.2f)) alpha = 0.0f;

            float bx2, by2, la2;
            if (alpha * 255.0f <= 1.0f) {
                bx2 = -1.0f; by2 = -1.0f; la2 = -1e30f;
            } else {
                float theta = 2.0f * __logf(255.0f * alpha);
                bx2 = A  * theta * 1.002f + 1e-2f;
                by2 = Cc * theta * 1.002f + 1e-2f;
                la2 = __log2f(alpha);
            }

            float wx = R00*t0 + R10*t1 + R20*t2;
            float wy = R01*t0 + R11*t1 + R21*t2;
            float wz = R02*t0 + R12*t1 + R22*t2;
            float dx0 = pwx + wx, dy0 = pwy + wy, dz0 = pwz + wz;
            float dn = rsqrtf(dx0*dx0 + dy0*dy0 + dz0*dz0);
            float x = dx0*dn, y = dy0*dn, z = dz0*dn;
            float xx=x*x, yy=y*y, zz=z*z, xy=x*y, yz=y*z, xz=x*z;

            float b1 = -0.4886025119029199f*y, b2 = 0.4886025119029199f*z, b3 = -0.4886025119029199f*x;
            float b4 =  1.0925484305920792f  * xy;
            float b5 = -1.0925484305920792f  * yz;
            float b6 =  0.31539156525252005f * (2.f*zz - xx - yy);
            float b7 = -1.0925484305920792f  * xz;
            float b8 =  0.5462742152960396f  * (xx - yy);
            float b9  = -0.5900435899266435f * y * (3.f*xx - yy);
            float b10 =  2.890611442640554f  * xy * z;
            float b11 = -0.4570457994644658f * y * (4.f*zz - xx - yy);
            float b12 =  0.3731763325901154f * z * (2.f*zz - 3.f*xx - 3.f*yy);
            float b13 = -0.4570457994644658f * x * (4.f*zz - xx - yy);
            float b14 =  1.445305721320277f  * z * (xx - yy);
            float b15 = -0.5900435899266435f * x * (xx - 3.f*yy);

            const float* hs = s_high + 45*tid;
            float col[3];
            #pragma unroll
            for (int ch = 0; ch < 3; ch++) {
                float c = 0.28209479177387814f * s_low[3*tid + ch];
                c += b1  * hs[0*3+ch]  + b2  * hs[1*3+ch]  + b3  * hs[2*3+ch];
                c += b4  * hs[3*3+ch]  + b5  * hs[4*3+ch]  + b6  * hs[5*3+ch];
                c += b7  * hs[6*3+ch]  + b8  * hs[7*3+ch];
                c += b9  * hs[8*3+ch]  + b10 * hs[9*3+ch]  + b11 * hs[10*3+ch];
                c += b12 * hs[11*3+ch] + b13 * hs[12*3+ch] + b14 * hs[13*3+ch];
                c += b15 * hs[14*3+ch];
                col[ch] = fmaxf(c + 0.5f, 0.0f);
            }

            g_p0[i] = make_float4(u0, u1, bx2, by2);
            g_p1[i] = make_float4(hA2, hB2, hC2, la2);
            g_p2[i] = make_float4(col[0], col[1], col[2], 0.0f);

            unsigned int bb = __float_as_uint(depth);
            bb = (bb & 0x80000000u) ? ~bb : (bb | 0x80000000u);
            g_key[i] = ((unsigned long long)bb << 32) | (unsigned int)i;
        }
    }

    gbar(gen);

    // ================= Phase 2: register-tiled rank argsort + gather (blocks 0..127) =================
    if (b < 128 && base < n) {
        unsigned long long* sk = (unsigned long long*)sbuf;
        int (*sred)[8] = (int(*)[8])(sbuf + 33280);

        for (int k = tid; k < NMAX; k += 512)
            sk[k] = (k < n) ? g_key[k] : 0xFFFFFFFFFFFFFFFFULL;
        __syncthreads();

        int g  = tid >> 7;      // group 0..3 (8 gaussians each)
        int sp = tid & 127;

        unsigned long long ki[8];
        #pragma unroll
        for (int u = 0; u < 8; u++) ki[u] = sk[base + g*8 + u];

        int r[8];
        #pragma unroll
        for (int u = 0; u < 8; u++) r[u] = 0;

        #pragma unroll 4
        for (int j = sp; j < NMAX; j += 128) {
            unsigned long long kj = sk[j];
            #pragma unroll
            for (int u = 0; u < 8; u++) r[u] += (kj < ki[u]) ? 1 : 0;
        }

        #pragma unroll
        for (int u = 0; u < 8; u++) {
            r[u] += __shfl_down_sync(0xffffffffu, r[u], 16);
            r[u] += __shfl_down_sync(0xffffffffu, r[u], 8);
            r[u] += __shfl_down_sync(0xffffffffu, r[u], 4);
            r[u] += __shfl_down_sync(0xffffffffu, r[u], 2);
            r[u] += __shfl_down_sync(0xffffffffu, r[u], 1);
        }
        if (lane == 0) {
            #pragma unroll
            for (int u = 0; u < 8; u++) sred[warp][u] = r[u];
        }
        __syncthreads();

        if (tid < 32) {
            int i = base + tid;
            if (i < n) {
                int g2 = tid >> 3, u = tid & 7;
                int rk = sred[g2*4+0][u] + sred[g2*4+1][u] + sred[g2*4+2][u] + sred[g2*4+3][u];
                o_p0[rk] = g_p0[i];
                o_p1[rk] = g_p1[i];
                o_p2[rk] = g_p2[i];
            }
        }
    }

    gbar(gen);

    // ================= Phase 3: cull + segmented blend (all 144 blocks = tiles) =================
    {
        unsigned* swords = (unsigned*)sbuf;
        int* wsum = (int*)(sbuf + OFF_WSUM);
        unsigned short* slist = (unsigned short*)(sbuf + OFF_SLIST);
        float4* stA = (float4*)(sbuf + OFF_STA);
        float4* stB = (float4*)(sbuf + OFF_STB);
        float*  stC = (float*)(sbuf + OFF_STC);
        float4* part = (float4*)(sbuf + OFF_PART);

        int tile = b;
        float x0 = (float)((tile % 12) * 8), x1 = x0 + 7.0f;
        float y0 = (float)((tile / 12) * 8), y1 = y0 + 7.0f;
        int nwords = (n + 31) >> 5;

        {
            float4 pv[8];
            #pragma unroll
            for (int k = 0; k < 8; k++) {
                int gi = k * 512 + tid;
                pv[k] = (gi < n) ? o_p0[gi] : make_float4(0.f, 0.f, -1.f, -1.f);
            }
            #pragma unroll
            for (int k = 0; k < 8; k++) {
                int gi = k * 512 + tid;
                float ddx = fmaxf(fmaxf(x0 - pv[k].x, pv[k].x - x1), 0.0f);
                float ddy = fmaxf(fmaxf(y0 - pv[k].y, pv[k].y - y1), 0.0f);
                bool keep = (gi < n) && (ddx*ddx <= pv[k].z) && (ddy*ddy <= pv[k].w);
                unsigned m = __ballot_sync(0xffffffffu, keep);
                if (lane == 0) swords[k * 16 + warp] = m;
            }
        }
        __syncthreads();

        int c = 0, v = 0;
        if (tid < 128) {
            c = (tid < nwords) ? __popc(swords[tid]) : 0;
            v = c;
            #pragma unroll
            for (int o = 1; o < 32; o <<= 1) {
                int u = __shfl_up_sync(0xffffffffu, v, o);
                if (lane >= o) v += u;
            }
            if (lane == 31) wsum[warp] = v;
        }
        __syncthreads();
        int cnt = wsum[0] + wsum[1] + wsum[2] + wsum[3];
        if (tid < nwords && c) {
            int add = 0;
            #pragma unroll
            for (int w = 0; w < 4; w++) if (w < warp) add += wsum[w];
            int slot = v - c + add;
            unsigned m = swords[tid];
            int bse = tid * 32;
            while (m) {
                int bt = __ffs(m) - 1; m &= m - 1;
                slist[slot++] = (unsigned short)(bse + bt);
            }
        }
        __syncthreads();

        int Lw = (cnt + NSEG - 1) / NSEG;
        int seg0 = warp * Lw;
        int seg1 = min(seg0 + Lw, cnt);

        int px = lane & 7, py = lane >> 3;
        float fpx  = x0 + (float)px;
        float fpy0 = y0 + (float)py;
        float fpy1 = fpy0 + 4.0f;

        float tau0 = 1.f, tau1 = 1.f;
        float A00=0.f, A01=0.f, A02=0.f, A10=0.f, A11=0.f, A12=0.f;

        for (int cs = seg0; cs < seg1; cs += 32) {
            int t = cs + lane;
            if (t < seg1) {
                int gi = slist[t];
                float4 p0 = o_p0[gi];
                float4 p1 = o_p1[gi];
                float4 p2 = o_p2[gi];
                stA[warp*32+lane] = make_float4(p0.x, p0.y, p1.x, p1.y);
                stB[warp*32+lane] = make_float4(p1.z, p1.w, p2.x, p2.y);
                stC[warp*32+lane] = p2.z;
            }
            __syncwarp();
            int m = min(32, seg1 - cs);
            for (int s = 0; s < m; s++) {
                float4 q0 = stA[warp*32+s];
                float4 q1 = stB[warp*32+s];
                float cb = stC[warp*32+s];
                float la2  = q1.y;
                float ddx  = q0.x - fpx;
                float bxd  = q0.w * ddx;
                float bsed = q0.z * ddx * ddx + la2;
                float ddy0 = q0.y - fpy0;
                float ddy1 = q0.y - fpy1;
                float qa = fminf(fmaf(fmaf(q1.x, ddy0, bxd), ddy0, bsed), la2);
                float qb = fminf(fmaf(fmaf(q1.x, ddy1, bxd), ddy1, bsed), la2);
                float ap0 = fminf(exp2_approx(qa), 0.99f);
                float ap1 = fminf(exp2_approx(qb), 0.99f);
                if (qa < LOG2_INV255) ap0 = 0.f;
                if (qb < LOG2_INV255) ap1 = 0.f;
                float w0 = ap0 * tau0, w1 = ap1 * tau1;
                A00 += q1.z * w0; A01 += q1.w * w0; A02 += cb * w0;
                A10 += q1.z * w1; A11 += q1.w * w1; A12 += cb * w1;
                tau0 -= tau0 * ap0;
                tau1 -= tau1 * ap1;
            }
            __syncwarp();
        }
        part[warp*64 + lane]      = make_float4(A00, A01, A02, tau0);
        part[warp*64 + lane + 32] = make_float4(A10, A11, A12, tau1);
        __syncthreads();

        if (tid < 64) {
            float T = 1.f, a0 = 0.f, a1 = 0.f, a2 = 0.f;
            #pragma unroll
            for (int w = 0; w < NSEG; w++) {
                float4 q = part[w*64 + tid];
                if (T > 1e-4f) {
                    a0 += T * q.x; a1 += T * q.y; a2 += T * q.z;
                    T *= q.w;
                }
            }
            int ppx = tid & 7, ppy = tid >> 3;
            int pix = ((tile / 12) * 8 + ppy) * 96 + (tile % 12) * 8 + ppx;
            out[pix]          = a0;
            out[NPIX + pix]   = a1;
            out[2*NPIX + pix] = a2;
        }
    }
}

extern "C" void kernel_launch(void* const* d_in, const int* in_sizes, int n_in,
                              void* d_out, int out_size)
{
    const float* pws   = (const float*)d_in[0];
    const float* lows  = (const float*)d_in[1];
    const float* highs = (const float*)d_in[2];
    const float* araw  = (const float*)d_in[3];
    const float* sraw  = (const float*)d_in[4];
    const float* qraw  = (const float*)d_in[5];
    const float* Rcw   = (const float*)d_in[7];
    const float* tcw   = (const float*)d_in[8];
    const float* cam   = (const float*)d_in[9];
    float* out = (float*)d_out;

    int n = in_sizes[0] / 3;
    if (n > NMAX) n = NMAX;

    fused_kernel<<<NBLK, 512>>>(pws, lows, highs, araw, sraw, qraw,
                                Rcw, tcw, cam, out, n);
}

// round 15
// speedup vs baseline: 1.2424x; 1.2424x over previous
#include <cuda_runtime.h>
#include <math.h>

#define NMAX 4096
#define NPIX (96*96)
#define NTILE 144
#define NSEG 16
#define PB 32
#define LOG2E 1.4426950408889634f
#define LOG2_INV255 -7.9943534f

// ---- packed scratch (device globals, UNSORTED index order) ----
__device__ float4 g_p0[NMAX];   // u0, u1, bx2, by2
__device__ float4 g_p1[NMAX];   // hA2, hB2, hC2, la2 (log2-scaled)
__device__ float4 g_p2[NMAX];   // cr, cg, cb, 0
__device__ unsigned g_dkey[NMAX];  // sortable depth bits

__device__ __forceinline__ float exp2_approx(float x)
{
    float r;
    asm("ex2.approx.ftz.f32 %0, %1;" : "=f"(r) : "f"(x));
    return r;
}

// ---------------- Kernel A: preprocess (128 blocks x 128 threads) ----------------
__global__ void __launch_bounds__(128, 1)
prep_kernel(const float* __restrict__ pws,
            const float* __restrict__ lows,
            const float* __restrict__ highs,
            const float* __restrict__ araw,
            const float* __restrict__ sraw,
            const float* __restrict__ qraw,
            const float* __restrict__ Rcw,
            const float* __restrict__ tcw,
            const float* __restrict__ cam,
            float* __restrict__ out_areas,
            int n)
{
    __shared__ float s_high[PB*45];
    __shared__ float s_pw[PB*3], s_low[PB*3], s_sr[PB*3], s_q[PB*4], s_a[PB];

    int base = blockIdx.x * PB;
    int tid  = threadIdx.x;

    if (base + PB <= n) {
        const float4* H4 = (const float4*)(highs + base*45);
        #pragma unroll
        for (int k = tid; k < PB*45/4; k += 128) ((float4*)s_high)[k] = H4[k];
        if (tid < PB*3/4) {
            ((float4*)s_pw)[tid]  = ((const float4*)(pws  + base*3))[tid];
            ((float4*)s_low)[tid] = ((const float4*)(lows + base*3))[tid];
            ((float4*)s_sr)[tid]  = ((const float4*)(sraw + base*3))[tid];
        }
        if (tid < PB)   ((float4*)s_q)[tid] = ((const float4*)(qraw + base*4))[tid];
        if (tid < PB/4) ((float4*)s_a)[tid] = ((const float4*)(araw + base))[tid];
    } else {
        for (int k = tid; k < PB*45 && base*45 + k < n*45; k += 128) s_high[k] = highs[base*45+k];
        for (int k = tid; k < PB*3 && base*3 + k < n*3; k += 128) {
            s_pw[k] = pws[base*3+k]; s_low[k] = lows[base*3+k]; s_sr[k] = sraw[base*3+k];
        }
        for (int k = tid; k < PB*4 && base*4 + k < n*4; k += 128) s_q[k] = qraw[base*4+k];
        if (tid < PB && base + tid < n) s_a[tid] = araw[base + tid];
    }
    __syncthreads();

    int i = base + tid;
    if (tid >= PB || i >= n) return;

    float fx = cam[0], fy = cam[1], cx = cam[2], cy = cam[3];
    float R00=Rcw[0],R01=Rcw[1],R02=Rcw[2];
    float R10=Rcw[3],R11=Rcw[4],R12=Rcw[5];
    float R20=Rcw[6],R21=Rcw[7],R22=Rcw[8];
    float t0=tcw[0],t1=tcw[1],t2=tcw[2];

    float pwx=s_pw[3*tid], pwy=s_pw[3*tid+1], pwz=s_pw[3*tid+2];
    float pcx = R00*pwx + R01*pwy + R02*pwz + t0;
    float pcy = R10*pwx + R11*pwy + R12*pwz + t1;
    float pcz = R20*pwx + R21*pwy + R22*pwz + t2;
    float depth = pcz;
    float zs = (depth > 1e-6f) ? depth : 1e-6f;
    float inv_z = 1.0f / zs;
    float u0 = fx * pcx * inv_z + cx;
    float u1 = fy * pcy * inv_z + cy;

    float s0 = __expf(s_sr[3*tid]), s1 = __expf(s_sr[3*tid+1]), s2 = __expf(s_sr[3*tid+2]);
    float qw=s_q[4*tid], qx=s_q[4*tid+1], qy=s_q[4*tid+2], qz=s_q[4*tid+3];
    float qn = rsqrtf(qw*qw + qx*qx + qy*qy + qz*qz);
    qw*=qn; qx*=qn; qy*=qn; qz*=qn;
    float r00 = 1.f-2.f*(qy*qy+qz*qz), r01 = 2.f*(qx*qy-qw*qz), r02 = 2.f*(qx*qz+qw*qy);
    float r10 = 2.f*(qx*qy+qw*qz), r11 = 1.f-2.f*(qx*qx+qz*qz), r12 = 2.f*(qy*qz-qw*qx);
    float r20 = 2.f*(qx*qz-qw*qy), r21 = 2.f*(qy*qz+qw*qx), r22 = 1.f-2.f*(qx*qx+qy*qy);

    float v0=s0*s0, v1=s1*s1, v2=s2*s2;
    float c00 = v0*r00*r00 + v1*r01*r01 + v2*r02*r02;
    float c01 = v0*r00*r10 + v1*r01*r11 + v2*r02*r12;
    float c02 = v0*r00*r20 + v1*r01*r21 + v2*r02*r22;
    float c11 = v0*r10*r10 + v1*r11*r11 + v2*r12*r12;
    float c12 = v0*r10*r20 + v1*r11*r21 + v2*r12*r22;
    float c22 = v0*r20*r20 + v1*r21*r21 + v2*r22*r22;

    float limx = 1.3f * (96.0f / (2.0f*fx));
    float limy = 1.3f * (96.0f / (2.0f*fy));
    float txc = fminf(fmaxf(pcx*inv_z, -limx), limx) * zs;
    float tyc = fminf(fmaxf(pcy*inv_z, -limy), limy) * zs;
    float J00 = fx*inv_z, J02 = -fx*txc*inv_z*inv_z;
    float J11 = fy*inv_z, J12 = -fy*tyc*inv_z*inv_z;

    float T00 = J00*R00 + J02*R20, T01 = J00*R01 + J02*R21, T02 = J00*R02 + J02*R22;
    float T10 = J11*R10 + J12*R20, T11 = J11*R11 + J12*R21, T12 = J11*R12 + J12*R22;

    float m00 = T00*c00 + T01*c01 + T02*c02;
    float m01 = T00*c01 + T01*c11 + T02*c12;
    float m02 = T00*c02 + T01*c12 + T02*c22;
    float m10 = T10*c00 + T11*c01 + T12*c02;
    float m11 = T10*c01 + T11*c11 + T12*c12;
    float m12 = T10*c02 + T11*c12 + T12*c22;

    float A  = m00*T00 + m01*T01 + m02*T02 + 0.3f;
    float Bb = m00*T10 + m01*T11 + m02*T12;
    float Cc = m10*T10 + m11*T11 + m12*T12 + 0.3f;

    float det  = A*Cc - Bb*Bb;
    float idet = 1.0f / det;
    float hA2 = -0.5f * Cc * idet * LOG2E;
    float hC2 = -0.5f * A  * idet * LOG2E;
    float hB2 =  Bb * idet * LOG2E;

    float mid = 0.5f * (A + Cc);
    float lam = mid + sqrtf(fmaxf(mid*mid - det, 0.1f));
    float radius = ceilf(3.0f * sqrtf(lam));
    out_areas[2*i]   = radius;
    out_areas[2*i+1] = radius;

    float alpha = 1.0f / (1.0f + __expf(-s_a[tid]));
    if (!(depth > 0.2f)) alpha = 0.0f;

    float bx2, by2, la2;
    if (alpha * 255.0f <= 1.0f) {
        bx2 = -1.0f; by2 = -1.0f; la2 = -1e30f;
    } else {
        float theta = 2.0f * __logf(255.0f * alpha);
        bx2 = A  * theta * 1.002f + 1e-2f;
        by2 = Cc * theta * 1.002f + 1e-2f;
        la2 = __log2f(alpha);
    }

    // SH color
    float wx = R00*t0 + R10*t1 + R20*t2;
    float wy = R01*t0 + R11*t1 + R21*t2;
    float wz = R02*t0 + R12*t1 + R22*t2;
    float dx0 = pwx + wx, dy0 = pwy + wy, dz0 = pwz + wz;
    float dn = rsqrtf(dx0*dx0 + dy0*dy0 + dz0*dz0);
    float x = dx0*dn, y = dy0*dn, z = dz0*dn;
    float xx=x*x, yy=y*y, zz=z*z, xy=x*y, yz=y*z, xz=x*z;

    float b1 = -0.4886025119029199f*y, b2 = 0.4886025119029199f*z, b3 = -0.4886025119029199f*x;
    float b4 =  1.0925484305920792f  * xy;
    float b5 = -1.0925484305920792f  * yz;
    float b6 =  0.31539156525252005f * (2.f*zz - xx - yy);
    float b7 = -1.0925484305920792f  * xz;
    float b8 =  0.5462742152960396f  * (xx - yy);
    float b9  = -0.5900435899266435f * y * (3.f*xx - yy);
    float b10 =  2.890611442640554f  * xy * z;
    float b11 = -0.4570457994644658f * y * (4.f*zz - xx - yy);
    float b12 =  0.3731763325901154f * z * (2.f*zz - 3.f*xx - 3.f*yy);
    float b13 = -0.4570457994644658f * x * (4.f*zz - xx - yy);
    float b14 =  1.445305721320277f  * z * (xx - yy);
    float b15 = -0.5900435899266435f * x * (xx - 3.f*yy);

    const float* hs = s_high + 45*tid;
    float col[3];
    #pragma unroll
    for (int ch = 0; ch < 3; ch++) {
        float c = 0.28209479177387814f * s_low[3*tid + ch];
        c += b1  * hs[0*3+ch]  + b2  * hs[1*3+ch]  + b3  * hs[2*3+ch];
        c += b4  * hs[3*3+ch]  + b5  * hs[4*3+ch]  + b6  * hs[5*3+ch];
        c += b7  * hs[6*3+ch]  + b8  * hs[7*3+ch];
        c += b9  * hs[8*3+ch]  + b10 * hs[9*3+ch]  + b11 * hs[10*3+ch];
        c += b12 * hs[11*3+ch] + b13 * hs[12*3+ch] + b14 * hs[13*3+ch];
        c += b15 * hs[14*3+ch];
        col[ch] = fmaxf(c + 0.5f, 0.0f);
    }

    g_p0[i] = make_float4(u0, u1, bx2, by2);
    g_p1[i] = make_float4(hA2, hB2, hC2, la2);
    g_p2[i] = make_float4(col[0], col[1], col[2], 0.0f);

    unsigned int bb = __float_as_uint(depth);
    bb = (bb & 0x80000000u) ? ~bb : (bb | 0x80000000u);
    g_dkey[i] = bb;
}

// ---------------- Kernel B: cull + LOCAL depth sort + segmented blend ----------------
// smem aliasing layout (bytes):
#define OFF_WSUM   512
#define OFF_SLIST  544          // u16 x 4096 -> ends 8736
#define OFF_SKEY   8736         // u64 x 4096 -> ends 41504 (sort scratch; freed before staging)
#define OFF_STA    8736         // float4 x NSEG*32 -> 16928
#define OFF_STB    16928        // -> 25120
#define OFF_STC    25120        // float  x NSEG*32 -> 27168
#define OFF_PART   27168        // float4 x NSEG*64 -> 43552
#define SBUF_BYTES 43584

__global__ void __launch_bounds__(512, 1)
blend_kernel(float* __restrict__ out, int n)
{
    __shared__ __align__(16) unsigned char sbuf[SBUF_BYTES];
    unsigned* swords = (unsigned*)sbuf;
    int* wsum = (int*)(sbuf + OFF_WSUM);
    unsigned short* slist = (unsigned short*)(sbuf + OFF_SLIST);

    int tile = blockIdx.x;
    int tid = threadIdx.x, lane = tid & 31, warp = tid >> 5;
    float x0 = (float)((tile % 12) * 8), x1 = x0 + 7.0f;
    float y0 = (float)((tile / 12) * 8), y1 = y0 + 7.0f;
    int nwords = (n + 31) >> 5;

    // ---- phase A: ellipse-AABB cull over UNSORTED gaussians ----
    {
        float4 pv[8];
        #pragma unroll
        for (int k = 0; k < 8; k++) {
            int gi = k * 512 + tid;
            pv[k] = (gi < n) ? g_p0[gi] : make_float4(0.f, 0.f, -1.f, -1.f);
        }
        #pragma unroll
        for (int k = 0; k < 8; k++) {
            int gi = k * 512 + tid;
            float ddx = fmaxf(fmaxf(x0 - pv[k].x, pv[k].x - x1), 0.0f);
            float ddy = fmaxf(fmaxf(y0 - pv[k].y, pv[k].y - y1), 0.0f);
            bool keep = (gi < n) && (ddx*ddx <= pv[k].z) && (ddy*ddy <= pv[k].w);
            unsigned m = __ballot_sync(0xffffffffu, keep);
            if (lane == 0) swords[k * 16 + warp] = m;
        }
    }
    __syncthreads();

    // ---- phase B: scan + expand survivor index list (ascending idx) ----
    int c = 0, v = 0;
    if (tid < 128) {
        c = (tid < nwords) ? __popc(swords[tid]) : 0;
        v = c;
        #pragma unroll
        for (int o = 1; o < 32; o <<= 1) {
            int u = __shfl_up_sync(0xffffffffu, v, o);
            if (lane >= o) v += u;
        }
        if (lane == 31) wsum[warp] = v;
    }
    __syncthreads();
    int cnt = wsum[0] + wsum[1] + wsum[2] + wsum[3];
    if (tid < nwords && c) {
        int add = 0;
        #pragma unroll
        for (int w = 0; w < 4; w++) if (w < warp) add += wsum[w];
        int slot = v - c + add;
        unsigned m = swords[tid];
        int bse = tid * 32;
        while (m) {
            int bt = __ffs(m) - 1; m &= m - 1;
            slist[slot++] = (unsigned short)(bse + bt);
        }
    }
    __syncthreads();

    // ---- phase B2: local bitonic sort of survivors by (depth_bits, idx) ----
    // key = (dkey << 12) | idx : 44 bits, unique -> exact stable depth order
    if (cnt > 1) {
        unsigned long long* skeys = (unsigned long long*)(sbuf + OFF_SKEY);
        int P = 1; while (P < cnt) P <<= 1;
        for (int t = tid; t < P; t += 512) {
            if (t < cnt) {
                unsigned idx = slist[t];
                skeys[t] = ((unsigned long long)g_dkey[idx] << 12) | idx;
            } else {
                skeys[t] = 0xFFFFFFFFFFFFFFFFULL;
            }
        }
        __syncthreads();
        for (int size = 2; size <= P; size <<= 1) {
            for (int stride = size >> 1; stride > 0; stride >>= 1) {
                for (int t = tid; t < (P >> 1); t += 512) {
                    int low = t & (stride - 1);
                    int ii = ((t - low) << 1) + low;
                    int jj = ii + stride;
                    bool asc = ((ii & size) == 0);
                    unsigned long long k0 = skeys[ii], k1 = skeys[jj];
                    if ((k0 > k1) == asc) { skeys[ii] = k1; skeys[jj] = k0; }
                }
                __syncthreads();
            }
        }
        for (int t = tid; t < cnt; t += 512)
            slist[t] = (unsigned short)(skeys[t] & 0xFFFu);
        __syncthreads();
    }

    // ---- phase C: per-warp segment composite (slist now depth-ordered) ----
    float4* stA = (float4*)(sbuf + OFF_STA);
    float4* stB = (float4*)(sbuf + OFF_STB);
    float*  stC = (float*)(sbuf + OFF_STC);
    float4* part = (float4*)(sbuf + OFF_PART);

    int Lw = (cnt + NSEG - 1) / NSEG;
    int seg0 = warp * Lw;
    int seg1 = min(seg0 + Lw, cnt);

    int px = lane & 7, py = lane >> 3;
    float fpx  = x0 + (float)px;
    float fpy0 = y0 + (float)py;
    float fpy1 = fpy0 + 4.0f;

    float tau0 = 1.f, tau1 = 1.f;
    float A00=0.f, A01=0.f, A02=0.f, A10=0.f, A11=0.f, A12=0.f;

    for (int cs = seg0; cs < seg1; cs += 32) {
        int t = cs + lane;
        if (t < seg1) {
            int gi = slist[t];
            float4 p0 = g_p0[gi];
            float4 p1 = g_p1[gi];
            float4 p2 = g_p2[gi];
            stA[warp*32+lane] = make_float4(p0.x, p0.y, p1.x, p1.y);
            stB[warp*32+lane] = make_float4(p1.z, p1.w, p2.x, p2.y);
            stC[warp*32+lane] = p2.z;
        }
        __syncwarp();
        int m = min(32, seg1 - cs);
        for (int s = 0; s < m; s++) {
            float4 q0 = stA[warp*32+s];
            float4 q1 = stB[warp*32+s];
            float cb = stC[warp*32+s];
            float la2  = q1.y;
            float ddx  = q0.x - fpx;
            float bxd  = q0.w * ddx;
            float bsed = q0.z * ddx * ddx + la2;
            float ddy0 = q0.y - fpy0;
            float ddy1 = q0.y - fpy1;
            float qa = fminf(fmaf(fmaf(q1.x, ddy0, bxd), ddy0, bsed), la2);
            float qb = fminf(fmaf(fmaf(q1.x, ddy1, bxd), ddy1, bsed), la2);
            float ap0 = fminf(exp2_approx(qa), 0.99f);
            float ap1 = fminf(exp2_approx(qb), 0.99f);
            if (qa < LOG2_INV255) ap0 = 0.f;
            if (qb < LOG2_INV255) ap1 = 0.f;
            float w0 = ap0 * tau0, w1 = ap1 * tau1;
            A00 += q1.z * w0; A01 += q1.w * w0; A02 += cb * w0;
            A10 += q1.z * w1; A11 += q1.w * w1; A12 += cb * w1;
            tau0 -= tau0 * ap0;
            tau1 -= tau1 * ap1;
        }
        __syncwarp();
    }
    part[warp*64 + lane]      = make_float4(A00, A01, A02, tau0);
    part[warp*64 + lane + 32] = make_float4(A10, A11, A12, tau1);
    __syncthreads();

    // ---- phase D: fold partials per pixel ----
    if (tid < 64) {
        float T = 1.f, a0 = 0.f, a1 = 0.f, a2 = 0.f;
        #pragma unroll
        for (int w = 0; w < NSEG; w++) {
            float4 q = part[w*64 + tid];
            if (T > 1e-4f) {
                a0 += T * q.x; a1 += T * q.y; a2 += T * q.z;
                T *= q.w;
            }
        }
        int ppx = tid & 7, ppy = tid >> 3;
        int pix = ((tile / 12) * 8 + ppy) * 96 + (tile % 12) * 8 + ppx;
        out[pix]          = a0;
        out[NPIX + pix]   = a1;
        out[2*NPIX + pix] = a2;
    }
}

extern "C" void kernel_launch(void* const* d_in, const int* in_sizes, int n_in,
                              void* d_out, int out_size)
{
    const float* pws   = (const float*)d_in[0];
    const float* lows  = (const float*)d_in[1];
    const float* highs = (const float*)d_in[2];
    const float* araw  = (const float*)d_in[3];
    const float* sraw  = (const float*)d_in[4];
    const float* qraw  = (const float*)d_in[5];
    const float* Rcw   = (const float*)d_in[7];
    const float* tcw   = (const float*)d_in[8];
    const float* cam   = (const float*)d_in[9];
    float* out = (float*)d_out;

    int n = in_sizes[0] / 3;
    if (n > NMAX) n = NMAX;

    float* out_areas = out + 3 * NPIX;

    prep_kernel<<<(n + PB - 1) / PB, 128>>>(pws, lows, highs, araw, sraw, qraw,
                                            Rcw, tcw, cam, out_areas, n);
    blend_kernel<<<NTILE, 512>>>(out, n);
}